// round 8
// baseline (speedup 1.0000x reference)
#include <cuda_runtime.h>

#define NBINS  10
#define NT     256
#define GRID   1216        // 8 CTAs * 152 SMs (GB300) -> full occupancy
#define TSTRIDE (GRID * NT)

// Per-block partials: every block overwrites its own slot -> no zeroing pass.
__device__ float2   g_part[GRID][NBINS];
__device__ unsigned g_ticket;   // zero-init at load; last block resets each call

// Predicated histogram update: no smem traffic when slot >= 10 (g >= 1,
// ~42% of elements). Hand-written @p predication (ptxas would emit
// BSSY/BSYNC for a C++ if{}). Address computed in C++ so ptxas can CSE it.
__device__ __forceinline__ void ghmc_acc(float p, float t, unsigned hb) {
    float g10  = fabsf(p - t) * 10.0f;
    int   slot = (int)g10;                   // g >= 0; slot >= 10 -> pred off
    unsigned ra = hb + (unsigned)slot * (NT * 8u);  // dead when pred false

    // bce = t*p - softplus(p);  softplus(p) = max(p,0) + log(1+exp(-|p|))
    float e   = __expf(-fabsf(p));
    float bce = t * p - fmaxf(p, 0.0f) - __logf(1.0f + e);

    asm volatile(
        "{\n\t"
        ".reg .pred p1;\n\t"
        ".reg .f32 rs, rc;\n\t"
        "setp.lt.s32 p1, %0, 10;\n\t"
        "@p1 ld.shared.v2.f32 {rs, rc}, [%1];\n\t"
        "@p1 add.f32 rs, rs, %2;\n\t"
        "@p1 add.f32 rc, rc, 0f3F800000;\n\t"   // += 1.0f
        "@p1 st.shared.v2.f32 [%1], {rs, rc};\n\t"
        "}"
        :: "r"(slot), "r"(ra), "f"(bce));
}

__device__ __forceinline__ void ghmc_acc4(float4 p, float4 t, unsigned hb) {
    ghmc_acc(p.x, t.x, hb);
    ghmc_acc(p.y, t.y, hb);
    ghmc_acc(p.z, t.z, hb);
    ghmc_acc(p.w, t.w, hb);
}

__global__ __launch_bounds__(NT, 8) void ghmc_kernel(
    const float4* __restrict__ pred,
    const float4* __restrict__ targ,
    int n4, int full_iters,
    float* __restrict__ out) {
    __shared__ float2 hist[NBINS * NT];    // 20,480 B -> 8 CTAs/SM
    __shared__ float  s_s[NBINS], s_c[NBINS];
    __shared__ bool   s_last;

    const int tid = threadIdx.x;
    #pragma unroll
    for (int i = 0; i < NBINS; i++)
        hist[i * NT + tid] = make_float2(0.0f, 0.0f);
    __syncthreads();

    const unsigned hb = (unsigned)__cvta_generic_to_shared(&hist[tid]);

    int i = blockIdx.x * NT + tid;

    // 4 coalesced, front-batched LDG.128 per iter (each touches exactly 4 lines).
    for (int k = 0; k < full_iters; k++) {
        float4 pa = __ldcs(&pred[i]);
        float4 pb = __ldcs(&pred[i + TSTRIDE]);
        float4 ta = __ldcs(&targ[i]);
        float4 tb = __ldcs(&targ[i + TSTRIDE]);
        ghmc_acc4(pa, ta, hb);
        ghmc_acc4(pb, tb, hb);
        i += 2 * TSTRIDE;
    }
    for (; i < n4; i += TSTRIDE) {
        float4 p = __ldcs(&pred[i]);
        float4 t = __ldcs(&targ[i]);
        ghmc_acc4(p, t, hb);
    }
    __syncthreads();

    // ---- block reduction: 16 threads per bin, each sums 16 slots ----
    if (tid < NBINS * 16) {
        int bin = tid >> 4;
        int j   = tid & 15;
        float sx = 0.0f, sy = 0.0f;
        #pragma unroll
        for (int k = 0; k < NT / 16; k++) {
            float2 a = hist[bin * NT + j + k * 16];
            sx += a.x;
            sy += a.y;
        }
        #pragma unroll
        for (int o = 8; o > 0; o >>= 1) {
            sx += __shfl_down_sync(0xffffffffu, sx, o, 16);
            sy += __shfl_down_sync(0xffffffffu, sy, o, 16);
        }
        if (j == 0)
            g_part[blockIdx.x][bin] = make_float2(sx, sy);
    }

    // ---- last-block final reduction (fused finalize) ----
    __threadfence();
    __syncthreads();
    if (tid == 0) {
        unsigned t = atomicAdd(&g_ticket, 1u);
        s_last = (t == GRID - 1);
    }
    __syncthreads();
    if (!s_last) return;

    __threadfence();
    if (tid < NBINS * 16) {
        int bin = tid >> 4;
        int j   = tid & 15;
        float sx = 0.0f, sy = 0.0f;
        for (int b = j; b < GRID; b += 16) {   // 76 L2-hot loads per thread
            float2 a = g_part[b][bin];
            sx += a.x;
            sy += a.y;
        }
        #pragma unroll
        for (int o = 8; o > 0; o >>= 1) {
            sx += __shfl_down_sync(0xffffffffu, sx, o, 16);
            sy += __shfl_down_sync(0xffffffffu, sy, o, 16);
        }
        if (j == 0) { s_s[bin] = sx; s_c[bin] = sy; }
    }
    __syncthreads();
    if (tid == 0) {
        float n = 0.0f, acc = 0.0f;
        #pragma unroll
        for (int i2 = 0; i2 < NBINS; i2++) {
            if (s_c[i2] > 0.0f) {
                n   += 1.0f;
                acc += s_s[i2] / s_c[i2];
            }
        }
        out[0] = -acc / fmaxf(n, 1.0f);
        g_ticket = 0;   // reset for next graph replay
    }
}

extern "C" void kernel_launch(void* const* d_in, const int* in_sizes, int n_in,
                              void* d_out, int out_size) {
    const float4* pred = (const float4*)d_in[0];
    const float4* targ = (const float4*)d_in[1];
    float* out = (float*)d_out;
    int n  = in_sizes[0];
    int n4 = n >> 2;                          // n divisible by 4
    int full_iters = n4 / (2 * TSTRIDE);      // unrolled main-loop trip count

    ghmc_kernel<<<GRID, NT>>>(pred, targ, n4, full_iters, out);
}

// round 9
// speedup vs baseline: 1.0115x; 1.0115x over previous
#include <cuda_runtime.h>

#define NBINS  10
#define NSLOTS 12          // 10 real bins + 2 dead slots (x,z -> 10; y,w -> 11)
#define NT     256
#define GRID   4864        // 4 waves of 8 CTAs * 152 SMs -> tail smoothing
#define TSTRIDE (GRID * NT)

// Per-block partials: every block overwrites its own slot -> no zeroing pass.
__device__ float2   g_part[GRID][NBINS];
__device__ unsigned g_ticket;   // zero-init at load; last block resets each call

// CLAMP = 10 for even elements, 11 for odd: splits dead-slot traffic across
// two smem addresses, breaking most same-address STS->LDS chains.
template <int CLAMP>
__device__ __forceinline__ void ghmc_acc(float p, float t, float2* __restrict__ h) {
    float g10 = fabsf(p - t) * 10.0f;
    int  slot = min((int)g10, CLAMP);   // slots 10,11 are dead (discarded)

    // bce = t*p - softplus(p);  softplus(p) = max(p,0) + log(1+exp(-|p|))
    float e   = __expf(-fabsf(p));
    float l   = __logf(1.0f + e);
    float bce = t * p - fmaxf(p, 0.0f) - l;

    float2 a = h[slot * NT];   // stride NT*8B: conflict-free across lanes
    a.x += bce;
    a.y += 1.0f;
    h[slot * NT] = a;
}

__device__ __forceinline__ void ghmc_acc4(float4 p, float4 t,
                                          float2* __restrict__ h) {
    ghmc_acc<10>(p.x, t.x, h);
    ghmc_acc<11>(p.y, t.y, h);
    ghmc_acc<10>(p.z, t.z, h);
    ghmc_acc<11>(p.w, t.w, h);
}

__global__ __launch_bounds__(NT) void ghmc_kernel(
    const float4* __restrict__ pred,
    const float4* __restrict__ targ,
    int n4, int full_iters,
    float* __restrict__ out) {
    __shared__ float2 hist[NSLOTS * NT];   // 24,576 B -> 8 CTAs/SM
    __shared__ float  s_s[NBINS], s_c[NBINS];
    __shared__ bool   s_last;

    const int tid = threadIdx.x;
    #pragma unroll
    for (int i = 0; i < NSLOTS; i++)
        hist[i * NT + tid] = make_float2(0.0f, 0.0f);
    __syncthreads();

    float2* h = &hist[tid];

    int i = blockIdx.x * NT + tid;

    // 4 coalesced LDG.128 front-batched per iter (each touches exactly 4 lines).
    for (int k = 0; k < full_iters; k++) {
        float4 pa = __ldcs(&pred[i]);
        float4 pb = __ldcs(&pred[i + TSTRIDE]);
        float4 ta = __ldcs(&targ[i]);
        float4 tb = __ldcs(&targ[i + TSTRIDE]);
        ghmc_acc4(pa, ta, h);
        ghmc_acc4(pb, tb, h);
        i += 2 * TSTRIDE;
    }
    // Remainder: plain grid-stride, still coalesced.
    for (; i < n4; i += TSTRIDE) {
        float4 p = __ldcs(&pred[i]);
        float4 t = __ldcs(&targ[i]);
        ghmc_acc4(p, t, h);
    }
    __syncthreads();

    // ---- block reduction: 16 threads per bin, each sums 16 slots ----
    if (tid < NBINS * 16) {
        int bin = tid >> 4;
        int j   = tid & 15;
        float sx = 0.0f, sy = 0.0f;
        #pragma unroll
        for (int k = 0; k < NT / 16; k++) {
            float2 a = hist[bin * NT + j + k * 16];
            sx += a.x;
            sy += a.y;
        }
        #pragma unroll
        for (int o = 8; o > 0; o >>= 1) {
            sx += __shfl_down_sync(0xffffffffu, sx, o, 16);
            sy += __shfl_down_sync(0xffffffffu, sy, o, 16);
        }
        if (j == 0)
            g_part[blockIdx.x][bin] = make_float2(sx, sy);
    }

    // ---- last-block final reduction (fused finalize) ----
    __threadfence();
    __syncthreads();
    if (tid == 0) {
        unsigned t = atomicAdd(&g_ticket, 1u);
        s_last = (t == GRID - 1);
    }
    __syncthreads();
    if (!s_last) return;

    __threadfence();
    if (tid < NBINS * 16) {
        int bin = tid >> 4;
        int j   = tid & 15;
        float sx = 0.0f, sy = 0.0f;
        for (int b = j; b < GRID; b += 16) {   // 304 independent L2-hot loads
            float2 a = g_part[b][bin];
            sx += a.x;
            sy += a.y;
        }
        #pragma unroll
        for (int o = 8; o > 0; o >>= 1) {
            sx += __shfl_down_sync(0xffffffffu, sx, o, 16);
            sy += __shfl_down_sync(0xffffffffu, sy, o, 16);
        }
        if (j == 0) { s_s[bin] = sx; s_c[bin] = sy; }
    }
    __syncthreads();
    if (tid == 0) {
        float n = 0.0f, acc = 0.0f;
        #pragma unroll
        for (int i2 = 0; i2 < NBINS; i2++) {
            if (s_c[i2] > 0.0f) {
                n   += 1.0f;
                acc += s_s[i2] / s_c[i2];
            }
        }
        out[0] = -acc / fmaxf(n, 1.0f);
        g_ticket = 0;   // reset for next graph replay
    }
}

extern "C" void kernel_launch(void* const* d_in, const int* in_sizes, int n_in,
                              void* d_out, int out_size) {
    const float4* pred = (const float4*)d_in[0];
    const float4* targ = (const float4*)d_in[1];
    float* out = (float*)d_out;
    int n  = in_sizes[0];
    int n4 = n >> 2;                          // n divisible by 4
    int full_iters = n4 / (2 * TSTRIDE);      // unrolled main-loop trip count

    ghmc_kernel<<<GRID, NT>>>(pred, targ, n4, full_iters, out);
}

// round 10
// speedup vs baseline: 1.0951x; 1.0827x over previous
#include <cuda_runtime.h>

#define NBINS  10
#define NSLOTS 12          // 10 real bins + 2 dead slots (even elems -> 10, odd -> 11)
#define NT     256
#define GRID   1216        // 8 CTAs * 152 SMs (GB300), single resident wave
#define TSTRIDE (GRID * NT)

// Per-block partials: every block overwrites its own slot -> no zeroing pass.
__device__ float2   g_part[GRID][NBINS];
__device__ unsigned g_ticket;   // zero-init at load; last block resets each call

// CLAMP = 10 for even elements, 11 for odd: dead (g>=1) updates from adjacent
// elements land on different smem addresses -> no same-address STS->LDS replay.
template <int CLAMP>
__device__ __forceinline__ void ghmc_acc(float p, float t, float2* __restrict__ h) {
    float g10 = fabsf(p - t) * 10.0f;
    int  slot = min((int)g10, CLAMP);   // slots 10/11 are dead (discarded later)

    // bce = t*p - softplus(p);  softplus(p) = max(p,0) + log(1+exp(-|p|))
    float e   = __expf(-fabsf(p));
    float l   = __logf(1.0f + e);
    float bce = t * p - fmaxf(p, 0.0f) - l;

    float2 a = h[slot * NT];   // stride NT*8B: conflict-free across lanes
    a.x += bce;
    a.y += 1.0f;
    h[slot * NT] = a;
}

__device__ __forceinline__ void ghmc_acc4(float4 p, float4 t,
                                          float2* __restrict__ h) {
    ghmc_acc<10>(p.x, t.x, h);
    ghmc_acc<11>(p.y, t.y, h);
    ghmc_acc<10>(p.z, t.z, h);
    ghmc_acc<11>(p.w, t.w, h);
}

__global__ __launch_bounds__(NT) void ghmc_kernel(
    const float4* __restrict__ pred,
    const float4* __restrict__ targ,
    int n4, int full_iters,
    float* __restrict__ out) {
    __shared__ float2 hist[NSLOTS * NT];   // 24,576 B -> 8 CTAs/SM
    __shared__ float  s_s[NBINS], s_c[NBINS];
    __shared__ bool   s_last;

    const int tid = threadIdx.x;
    #pragma unroll
    for (int i = 0; i < NSLOTS; i++)
        hist[i * NT + tid] = make_float2(0.0f, 0.0f);
    __syncthreads();

    float2* h = &hist[tid];

    int i = blockIdx.x * NT + tid;

    // 4 coalesced LDG.128 front-batched per iter (each touches exactly 4 lines).
    for (int k = 0; k < full_iters; k++) {
        float4 pa = pred[i];
        float4 pb = pred[i + TSTRIDE];
        float4 ta = targ[i];
        float4 tb = targ[i + TSTRIDE];
        ghmc_acc4(pa, ta, h);
        ghmc_acc4(pb, tb, h);
        i += 2 * TSTRIDE;
    }
    // Remainder: plain grid-stride, still coalesced.
    for (; i < n4; i += TSTRIDE) {
        float4 p = pred[i];
        float4 t = targ[i];
        ghmc_acc4(p, t, h);
    }
    __syncthreads();

    // ---- block reduction: 16 threads per bin, each sums 16 slots ----
    if (tid < NBINS * 16) {
        int bin = tid >> 4;
        int j   = tid & 15;
        float sx = 0.0f, sy = 0.0f;
        #pragma unroll
        for (int k = 0; k < NT / 16; k++) {
            float2 a = hist[bin * NT + j + k * 16];
            sx += a.x;
            sy += a.y;
        }
        #pragma unroll
        for (int o = 8; o > 0; o >>= 1) {
            sx += __shfl_down_sync(0xffffffffu, sx, o, 16);
            sy += __shfl_down_sync(0xffffffffu, sy, o, 16);
        }
        if (j == 0)
            g_part[blockIdx.x][bin] = make_float2(sx, sy);
    }

    // ---- last-block final reduction (fused finalize) ----
    __threadfence();
    __syncthreads();
    if (tid == 0) {
        unsigned t = atomicAdd(&g_ticket, 1u);
        s_last = (t == GRID - 1);
    }
    __syncthreads();
    if (!s_last) return;

    __threadfence();
    if (tid < NBINS * 16) {
        int bin = tid >> 4;
        int j   = tid & 15;
        float sx = 0.0f, sy = 0.0f;
        for (int b = j; b < GRID; b += 16) {   // 76 L2-hot loads per thread
            float2 a = g_part[b][bin];
            sx += a.x;
            sy += a.y;
        }
        #pragma unroll
        for (int o = 8; o > 0; o >>= 1) {
            sx += __shfl_down_sync(0xffffffffu, sx, o, 16);
            sy += __shfl_down_sync(0xffffffffu, sy, o, 16);
        }
        if (j == 0) { s_s[bin] = sx; s_c[bin] = sy; }
    }
    __syncthreads();
    if (tid == 0) {
        float n = 0.0f, acc = 0.0f;
        #pragma unroll
        for (int i2 = 0; i2 < NBINS; i2++) {
            if (s_c[i2] > 0.0f) {
                n   += 1.0f;
                acc += s_s[i2] / s_c[i2];
            }
        }
        out[0] = -acc / fmaxf(n, 1.0f);
        g_ticket = 0;   // reset for next graph replay
    }
}

extern "C" void kernel_launch(void* const* d_in, const int* in_sizes, int n_in,
                              void* d_out, int out_size) {
    const float4* pred = (const float4*)d_in[0];
    const float4* targ = (const float4*)d_in[1];
    float* out = (float*)d_out;
    int n  = in_sizes[0];
    int n4 = n >> 2;                          // n divisible by 4
    int full_iters = n4 / (2 * TSTRIDE);      // unrolled main-loop trip count

    ghmc_kernel<<<GRID, NT>>>(pred, targ, n4, full_iters, out);
}

// round 11
// speedup vs baseline: 1.2498x; 1.1412x over previous
#include <cuda_runtime.h>

#define NBINS  10
#define NSLOTS 11          // 10 real bins + 1 dead slot (g >= 1)
#define NT     256
#define GRID   1216        // 8 CTAs * 152 SMs (GB300), single resident wave
#define TSTRIDE (GRID * NT)

// Per-block partials: every block overwrites its own slot -> no zeroing pass.
__device__ float2   g_part[GRID][NBINS];
__device__ unsigned g_ticket;   // zero-init at load; last block resets each call

__device__ __forceinline__ void ghmc_acc(float p, float t, float2* __restrict__ h) {
    // slot = min(floor(10*|p-t|), 10); slot 10 is dead (discarded later).
    float g10 = fabsf(p - t) * 10.0f;
    int  slot = min((int)g10, NSLOTS - 1);

    // bce = t*p - softplus(p);  softplus(p) = max(p,0) + log(1+exp(-|p|))
    float e   = __expf(-fabsf(p));
    float l   = __logf(1.0f + e);
    float bce = t * p - fmaxf(p, 0.0f) - l;

    float2 a = h[slot * NT];   // per-lane distinct addresses: conflict-free
    a.x += bce;
    a.y += 1.0f;
    h[slot * NT] = a;
}

// Even elements (x,z) use column tid; odd elements (y,w) use column
// (tid+128)&255. Same slot rows, disjoint addresses -> adjacent elements
// (dead OR same-bin) never RMW the same smem word. Per-warp offset is a
// uniform +128 (warps 32-aligned, no wrap inside a warp) -> banks unchanged.
__device__ __forceinline__ void ghmc_acc4(float4 p, float4 t,
                                          float2* __restrict__ h0,
                                          float2* __restrict__ h1) {
    ghmc_acc(p.x, t.x, h0);
    ghmc_acc(p.y, t.y, h1);
    ghmc_acc(p.z, t.z, h0);
    ghmc_acc(p.w, t.w, h1);
}

__global__ __launch_bounds__(NT) void ghmc_kernel(
    const float4* __restrict__ pred,
    const float4* __restrict__ targ,
    int n4, int full_iters,
    float* __restrict__ out) {
    __shared__ float2 hist[NSLOTS * NT];   // 22,528 B -> 8 CTAs/SM (R6-proven)
    __shared__ float  s_s[NBINS], s_c[NBINS];
    __shared__ bool   s_last;

    const int tid = threadIdx.x;
    #pragma unroll
    for (int i = 0; i < NSLOTS; i++)
        hist[i * NT + tid] = make_float2(0.0f, 0.0f);
    __syncthreads();

    float2* h0 = &hist[tid];
    float2* h1 = &hist[(tid + 128) & 255];

    int i = blockIdx.x * NT + tid;

    // 4 coalesced LDG.128 front-batched per iter (each touches exactly 4 lines).
    for (int k = 0; k < full_iters; k++) {
        float4 pa = pred[i];
        float4 pb = pred[i + TSTRIDE];
        float4 ta = targ[i];
        float4 tb = targ[i + TSTRIDE];
        ghmc_acc4(pa, ta, h0, h1);
        ghmc_acc4(pb, tb, h0, h1);
        i += 2 * TSTRIDE;
    }
    // Remainder: plain grid-stride, still coalesced.
    for (; i < n4; i += TSTRIDE) {
        float4 p = pred[i];
        float4 t = targ[i];
        ghmc_acc4(p, t, h0, h1);
    }
    __syncthreads();

    // ---- block reduction: 16 threads per bin, each sums 16 columns ----
    if (tid < NBINS * 16) {
        int bin = tid >> 4;
        int j   = tid & 15;
        float sx = 0.0f, sy = 0.0f;
        #pragma unroll
        for (int k = 0; k < NT / 16; k++) {
            float2 a = hist[bin * NT + j + k * 16];
            sx += a.x;
            sy += a.y;
        }
        #pragma unroll
        for (int o = 8; o > 0; o >>= 1) {
            sx += __shfl_down_sync(0xffffffffu, sx, o, 16);
            sy += __shfl_down_sync(0xffffffffu, sy, o, 16);
        }
        if (j == 0)
            g_part[blockIdx.x][bin] = make_float2(sx, sy);
    }

    // ---- last-block final reduction (fused finalize) ----
    __threadfence();
    __syncthreads();
    if (tid == 0) {
        unsigned t = atomicAdd(&g_ticket, 1u);
        s_last = (t == GRID - 1);
    }
    __syncthreads();
    if (!s_last) return;

    __threadfence();
    if (tid < NBINS * 16) {
        int bin = tid >> 4;
        int j   = tid & 15;
        float sx = 0.0f, sy = 0.0f;
        for (int b = j; b < GRID; b += 16) {   // 76 L2-hot loads per thread
            float2 a = g_part[b][bin];
            sx += a.x;
            sy += a.y;
        }
        #pragma unroll
        for (int o = 8; o > 0; o >>= 1) {
            sx += __shfl_down_sync(0xffffffffu, sx, o, 16);
            sy += __shfl_down_sync(0xffffffffu, sy, o, 16);
        }
        if (j == 0) { s_s[bin] = sx; s_c[bin] = sy; }
    }
    __syncthreads();
    if (tid == 0) {
        float n = 0.0f, acc = 0.0f;
        #pragma unroll
        for (int i2 = 0; i2 < NBINS; i2++) {
            if (s_c[i2] > 0.0f) {
                n   += 1.0f;
                acc += s_s[i2] / s_c[i2];
            }
        }
        out[0] = -acc / fmaxf(n, 1.0f);
        g_ticket = 0;   // reset for next graph replay
    }
}

extern "C" void kernel_launch(void* const* d_in, const int* in_sizes, int n_in,
                              void* d_out, int out_size) {
    const float4* pred = (const float4*)d_in[0];
    const float4* targ = (const float4*)d_in[1];
    float* out = (float*)d_out;
    int n  = in_sizes[0];
    int n4 = n >> 2;                          // n divisible by 4
    int full_iters = n4 / (2 * TSTRIDE);      // unrolled main-loop trip count

    ghmc_kernel<<<GRID, NT>>>(pred, targ, n4, full_iters, out);
}